// round 8
// baseline (speedup 1.0000x reference)
#include <cuda_runtime.h>
#include <cstddef>

#define BATCH 256
#define H 100
#define NIN 784
#define T 2500
#define BH (BATCH * H)                 // 25600
#define SEC ((size_t)T * (size_t)BH)   // 64,000,000 elements per section
#define NCHUNK 25
#define CHUNK 100                      // NCHUNK * CHUNK == T

#define P1_BLOCKS 200                  // phase-1 blocks, 128 consecutive cells
#define BTILE 32                       // gemm tile: 32 batches x 4 heads
#define HTILE 4
#define CELLS_PER_THREAD 4
#define P2_BLOCKS_PER_CHUNK (BH / (128 * CELLS_PER_THREAD))   // 50
#define P2_BLOCKS (NCHUNK * P2_BLOCKS_PER_CHUNK)              // 1250

// Scratch (no cudaMalloc allowed)
__device__ float  g_cur1[BH];
__device__ float4 g_ckpt[NCHUNK * BH];        // state at start of each chunk
// flags[c*32]: chunk-c ready count; flags[NCHUNK*32]: gemm-done count.
__device__ int    g_flags[NCHUNK * 32 + 32];
#define GEMM_FLAG (NCHUNK * 32)

// ---------------------------------------------------------------------------
// Shared step function — identical in phase1/phase2 so replay from checkpoints
// is bit-identical to a monolithic run.
// ---------------------------------------------------------------------------
__device__ __forceinline__ void lif_step(const float a1, const float be1,
                                         const float cur,
                                         float& syn1, float& mem1,
                                         float& syn2, float& mem2,
                                         float& spk1, float& spk2) {
    const float keep1 = (mem1 > 1.0f) ? 0.0f : 1.0f;   // reset from PREVIOUS mem
    syn1 = fmaf(a1, syn1, cur);
    mem1 = fmaf(be1, mem1, syn1) * keep1;
    spk1 = (mem1 > 1.0f) ? 1.0f : 0.0f;
    const float keep2 = (mem2 > 1.0f) ? 0.0f : 1.0f;
    syn2 = fmaf(0.8f, syn2, spk1);
    mem2 = fmaf(0.9f, mem2, syn2) * keep2;
    spk2 = (mem2 > 1.0f) ? 1.0f : 0.0f;
}

// ---------------------------------------------------------------------------
// ONE fused kernel:
//   blocks [0, P1_BLOCKS): phase 1.
//     Stage A: tiled GEMM (32b x 4h per block; W1 rows staged in smem ->
//       aggregate W1 L2 traffic 2.5MB, x 20MB), writes g_cur1, bumps
//       gemm counter.
//     Stage B: wait counter==200, read this block's 128 CONSECUTIVE cells'
//       cur from g_cur1, run the serial recurrence with consecutive-cell
//       checkpoints (proven R6 layout), releasing flag[c] BEFORE computing
//       chunk c.
//   blocks [P1_BLOCKS, ...): phase 2 (UNCHANGED 73%-DRAM store engine).
// ---------------------------------------------------------------------------
__global__ void __launch_bounds__(128) snn_fused(const float* __restrict__ x,
                                                 const float* __restrict__ W1,
                                                 const float* __restrict__ b1,
                                                 const float* __restrict__ alpha1,
                                                 const float* __restrict__ beta1,
                                                 float* __restrict__ out) {
    const float a1  = fminf(fmaxf(alpha1[0], 0.0f), 1.0f);
    const float be1 = fminf(fmaxf(beta1[0], 0.0f), 1.0f);
    const int tid = threadIdx.x;

    if (blockIdx.x < P1_BLOCKS) {
        // ------------ stage A: tiled GEMM -> g_cur1 (transpose buffer) ------
        __shared__ __align__(16) float ws[HTILE][NIN];   // 4 W1 rows, 12.5KB
        {
            const int bt = blockIdx.x & 7;               // 8 b-tiles
            const int ht = blockIdx.x >> 3;              // 25 h-tiles
            const int h_local = tid & (HTILE - 1);
            const int b = bt * BTILE + (tid >> 2);
            const int h = ht * HTILE + h_local;

            for (int i = tid; i < HTILE * NIN; i += 128) // coalesced W1 rows
                ws[0][i] = W1[(size_t)(ht * HTILE) * NIN + i];
            __syncthreads();

            const float4* __restrict__ x4 =
                reinterpret_cast<const float4*>(x + (size_t)b * NIN);
            const float4* __restrict__ w4 =
                reinterpret_cast<const float4*>(ws[h_local]);
            float c0 = 0.f, c1 = 0.f, c2 = 0.f, c3 = 0.f;
#pragma unroll 4
            for (int k4 = 0; k4 < NIN / 4; k4++) {
                const float4 xv = x4[k4];
                const float4 wv = w4[k4];
                c0 = fmaf(xv.x, wv.x, c0);
                c1 = fmaf(xv.y, wv.y, c1);
                c2 = fmaf(xv.z, wv.z, c2);
                c3 = fmaf(xv.w, wv.w, c3);
            }
            g_cur1[b * H + h] = ((c0 + c1) + (c2 + c3)) + b1[h];

            __threadfence();
            __syncthreads();
            if (tid == 0) atomicAdd(&g_flags[GEMM_FLAG], 1);
        }

        // ------------ stage B: wait all tiles, then R6 recurrence ----------
        if (tid == 0) {
            while (atomicAdd(&g_flags[GEMM_FLAG], 0) < P1_BLOCKS)
                __nanosleep(100);
        }
        __syncthreads();
        __threadfence();

        const int cell = blockIdx.x * 128 + tid;         // consecutive cells
        const float cur = g_cur1[cell];
        float syn1 = 0.f, mem1 = 0.f, syn2 = 0.f, mem2 = 0.f;
        float spk1, spk2;

        for (int c = 0; c < NCHUNK; c++) {
            g_ckpt[c * BH + cell] = make_float4(syn1, mem1, syn2, mem2);
            __threadfence();
            __syncthreads();                   // whole block's ckpt visible
            if (tid == 0) atomicAdd(&g_flags[c * 32], 1);
#pragma unroll 5
            for (int i = 0; i < CHUNK; i++)
                lif_step(a1, be1, cur, syn1, mem1, syn2, mem2, spk1, spk2);
        }
    } else {
        // ---------------- phase 2 (unchanged) ----------------
        const int idx = blockIdx.x - P1_BLOCKS;
        const int c = idx / P2_BLOCKS_PER_CHUNK;           // chunk-major order
        const int blk = idx % P2_BLOCKS_PER_CHUNK;
        const int cell0 = (blk * 128 + tid) * CELLS_PER_THREAD;

        if (tid == 0) {
            while (atomicAdd(&g_flags[c * 32], 0) < P1_BLOCKS)
                __nanosleep(200);
        }
        __syncthreads();
        __threadfence();

        const float4 cur4 = *reinterpret_cast<const float4*>(g_cur1 + cell0);
        float cur[4] = {cur4.x, cur4.y, cur4.z, cur4.w};

        float syn1[4], mem1[4], syn2[4], mem2[4], spk1[4], spk2[4];
#pragma unroll
        for (int j = 0; j < 4; j++) {
            float4 st = g_ckpt[c * BH + cell0 + j];
            syn1[j] = st.x; mem1[j] = st.y; syn2[j] = st.z; mem2[j] = st.w;
        }

        float* __restrict__ spk2o = out;
        float* __restrict__ mem2o = out + SEC;
        float* __restrict__ curo  = out + 2 * SEC;
        float* __restrict__ spk1o = out + 3 * SEC;
        float* __restrict__ mem1o = out + 4 * SEC;

        size_t off = (size_t)(c * CHUNK) * BH + cell0;
#pragma unroll 2
        for (int i = 0; i < CHUNK; i++, off += BH) {
#pragma unroll
            for (int j = 0; j < 4; j++)
                lif_step(a1, be1, cur[j], syn1[j], mem1[j], syn2[j], mem2[j],
                         spk1[j], spk2[j]);
            *reinterpret_cast<float4*>(spk2o + off) =
                make_float4(spk2[0], spk2[1], spk2[2], spk2[3]);
            *reinterpret_cast<float4*>(mem2o + off) =
                make_float4(mem2[0], mem2[1], mem2[2], mem2[3]);
            *reinterpret_cast<float4*>(curo + off) = cur4;
            *reinterpret_cast<float4*>(spk1o + off) =
                make_float4(spk1[0], spk1[1], spk1[2], spk1[3]);
            *reinterpret_cast<float4*>(mem1o + off) =
                make_float4(mem1[0], mem1[1], mem1[2], mem1[3]);
        }
    }
}

// ---------------------------------------------------------------------------
// Inputs: x[256*784], W1[100*784], b1[100], alpha1[1], beta1[1]  (all f32)
// Output: 5 sections of [T,B,H] f32: spk2, mem2, cur, spk1, mem1
// ---------------------------------------------------------------------------
extern "C" void kernel_launch(void* const* d_in, const int* in_sizes, int n_in,
                              void* d_out, int out_size) {
    const float* x      = (const float*)d_in[0];
    const float* W1     = (const float*)d_in[1];
    const float* b1     = (const float*)d_in[2];
    const float* alpha1 = (const float*)d_in[3];
    const float* beta1  = (const float*)d_in[4];
    float* out = (float*)d_out;

    // Reset sync flags (graph-capturable memset node; no allocation).
    void* flags_ptr = nullptr;
    cudaGetSymbolAddress(&flags_ptr, g_flags);
    cudaMemsetAsync(flags_ptr, 0, (NCHUNK * 32 + 32) * sizeof(int));

    snn_fused<<<P1_BLOCKS + P2_BLOCKS, 128>>>(x, W1, b1, alpha1, beta1, out);
}

// round 9
// speedup vs baseline: 1.0965x; 1.0965x over previous
#include <cuda_runtime.h>
#include <cstddef>

#define BATCH 256
#define H 100
#define NIN 784
#define T 2500
#define BH (BATCH * H)                 // 25600
#define SEC ((size_t)T * (size_t)BH)   // 64,000,000 elements per section
#define NCHUNK 25
#define CHUNK 100                      // NCHUNK * CHUNK == T

#define P1_BLOCKS (BH / 128)           // 200 phase-1 blocks (1 cell/thread)
#define CELLS_PER_THREAD 4
#define P2_BLOCKS_PER_CHUNK (BH / (128 * CELLS_PER_THREAD))   // 50
#define P2_BLOCKS (NCHUNK * P2_BLOCKS_PER_CHUNK)              // 1250

// Scratch (no cudaMalloc allowed)
__device__ float  g_cur1[BH];
__device__ float4 g_ckpt[NCHUNK * BH];        // state at start of each chunk
__device__ int    g_flags[NCHUNK * 32];       // 1 flag per chunk, 128B apart

// ---------------------------------------------------------------------------
// Shared step function — identical in phase1/phase2 so replay from checkpoints
// is bit-identical to a monolithic run.
// ---------------------------------------------------------------------------
__device__ __forceinline__ void lif_step(const float a1, const float be1,
                                         const float cur,
                                         float& syn1, float& mem1,
                                         float& syn2, float& mem2,
                                         float& spk1, float& spk2) {
    const float keep1 = (mem1 > 1.0f) ? 0.0f : 1.0f;   // reset from PREVIOUS mem
    syn1 = fmaf(a1, syn1, cur);
    mem1 = fmaf(be1, mem1, syn1) * keep1;
    spk1 = (mem1 > 1.0f) ? 1.0f : 0.0f;
    const float keep2 = (mem2 > 1.0f) ? 0.0f : 1.0f;
    syn2 = fmaf(0.8f, syn2, spk1);
    mem2 = fmaf(0.9f, mem2, syn2) * keep2;
    spk2 = (mem2 > 1.0f) ? 1.0f : 0.0f;
}

// Poll with a plain volatile L2 load — NOT atomicAdd(ptr,0). Atomic polls
// serialize on the per-address LTS atomic ALU (~32cyc/op) and starve the
// releasing increments when hundreds of blocks spin on one line (the R4/R7/R8
// regression mechanism). Volatile reads ride normal L2 read bandwidth.
__device__ __forceinline__ void spin_on_flag(const int* flag, int target) {
    while (*(volatile const int*)flag < target) __nanosleep(200);
}

// ---------------------------------------------------------------------------
// ONE fused kernel (R6 structure — the 225.3us asset — with only the polling
// mechanism changed):
//   blocks [0, P1_BLOCKS): phase 1 — compute cur1 for this block's 128
//     consecutive cells (coalesced float4 W1 reads, 8 lanes per cell, width-8
//     shuffle reduce), publish g_cur1, then run the serial recurrence,
//     checkpointing at each chunk start and releasing flag[c] BEFORE
//     computing chunk c.
//   blocks [P1_BLOCKS, ...): phase 2 — wait flag[c] (volatile poll), replay
//     CHUNK steps for 4 cells, float4 stores to all 5 sections.
// ---------------------------------------------------------------------------
__global__ void __launch_bounds__(128) snn_fused(const float* __restrict__ x,
                                                 const float* __restrict__ W1,
                                                 const float* __restrict__ b1,
                                                 const float* __restrict__ alpha1,
                                                 const float* __restrict__ beta1,
                                                 float* __restrict__ out) {
    const float a1  = fminf(fmaxf(alpha1[0], 0.0f), 1.0f);
    const float be1 = fminf(fmaxf(beta1[0], 0.0f), 1.0f);
    const int tid = threadIdx.x;

    if (blockIdx.x < P1_BLOCKS) {
        // ---------------- phase 1: fused GEMM ----------------
        __shared__ float xs[3 * NIN];          // up to 3 batch rows
        __shared__ float curs[128];
        const int cell0blk = blockIdx.x * 128;
        const int b0 = cell0blk / H;
        const int nb = ((cell0blk + 127) / H) - b0 + 1;    // 2 or 3

        for (int i = tid; i < nb * NIN; i += 128)
            xs[i] = x[(size_t)(b0 + i / NIN) * NIN + (i % NIN)];
        __syncthreads();

        const int warp = tid >> 5;
        const int lane = tid & 31;
        const int g  = lane >> 3;              // 4 cell-groups per warp-phase
        const int gl = lane & 7;               // lane within 8-lane group

#pragma unroll 1
        for (int p = 0; p < 8; p++) {
            const int lcell = warp * 32 + p * 4 + g;       // 0..127
            const int cid = cell0blk + lcell;
            const int cb = cid / H, ch = cid % H;
            const float4* __restrict__ w4 =
                reinterpret_cast<const float4*>(W1 + (size_t)ch * NIN);
            const float* __restrict__ xr = xs + (cb - b0) * NIN;

            float acc = 0.0f;
#pragma unroll
            for (int t = 0; t < 24; t++) {     // 196 float4 = 8*24 + 4
                const int j = gl + 8 * t;
                const float4 wv = w4[j];
                const int k = j * 4;
                acc = fmaf(wv.x, xr[k + 0], acc);
                acc = fmaf(wv.y, xr[k + 1], acc);
                acc = fmaf(wv.z, xr[k + 2], acc);
                acc = fmaf(wv.w, xr[k + 3], acc);
            }
            if (gl < 4) {                      // remainder float4 192..195
                const int j = 192 + gl;
                const float4 wv = w4[j];
                const int k = j * 4;
                acc = fmaf(wv.x, xr[k + 0], acc);
                acc = fmaf(wv.y, xr[k + 1], acc);
                acc = fmaf(wv.z, xr[k + 2], acc);
                acc = fmaf(wv.w, xr[k + 3], acc);
            }
            acc += __shfl_down_sync(0xFFFFFFFFu, acc, 4, 8);
            acc += __shfl_down_sync(0xFFFFFFFFu, acc, 2, 8);
            acc += __shfl_down_sync(0xFFFFFFFFu, acc, 1, 8);
            if (gl == 0) curs[lcell] = acc + b1[ch];
        }
        __syncthreads();

        const int cell = cell0blk + tid;
        const float cur = curs[tid];
        g_cur1[cell] = cur;                    // publish for phase 2

        // ---------------- phase 1: recurrence + checkpoints ----------------
        float syn1 = 0.f, mem1 = 0.f, syn2 = 0.f, mem2 = 0.f;
        float spk1, spk2;

        for (int c = 0; c < NCHUNK; c++) {
            g_ckpt[c * BH + cell] = make_float4(syn1, mem1, syn2, mem2);
            __threadfence();
            __syncthreads();                   // ckpt (and cur1) visible
            if (tid == 0) atomicAdd(&g_flags[c * 32], 1);
#pragma unroll 5
            for (int i = 0; i < CHUNK; i++)
                lif_step(a1, be1, cur, syn1, mem1, syn2, mem2, spk1, spk2);
        }
    } else {
        // ---------------- phase 2 (volatile poll; otherwise unchanged) -----
        const int idx = blockIdx.x - P1_BLOCKS;
        const int c = idx / P2_BLOCKS_PER_CHUNK;           // chunk-major order
        const int blk = idx % P2_BLOCKS_PER_CHUNK;
        const int cell0 = (blk * 128 + tid) * CELLS_PER_THREAD;

        if (tid == 0) spin_on_flag(&g_flags[c * 32], P1_BLOCKS);
        __syncthreads();
        __threadfence();

        const float4 cur4 = *reinterpret_cast<const float4*>(g_cur1 + cell0);
        float cur[4] = {cur4.x, cur4.y, cur4.z, cur4.w};

        float syn1[4], mem1[4], syn2[4], mem2[4], spk1[4], spk2[4];
#pragma unroll
        for (int j = 0; j < 4; j++) {
            float4 st = g_ckpt[c * BH + cell0 + j];
            syn1[j] = st.x; mem1[j] = st.y; syn2[j] = st.z; mem2[j] = st.w;
        }

        float* __restrict__ spk2o = out;
        float* __restrict__ mem2o = out + SEC;
        float* __restrict__ curo  = out + 2 * SEC;
        float* __restrict__ spk1o = out + 3 * SEC;
        float* __restrict__ mem1o = out + 4 * SEC;

        size_t off = (size_t)(c * CHUNK) * BH + cell0;
#pragma unroll 2
        for (int i = 0; i < CHUNK; i++, off += BH) {
#pragma unroll
            for (int j = 0; j < 4; j++)
                lif_step(a1, be1, cur[j], syn1[j], mem1[j], syn2[j], mem2[j],
                         spk1[j], spk2[j]);
            *reinterpret_cast<float4*>(spk2o + off) =
                make_float4(spk2[0], spk2[1], spk2[2], spk2[3]);
            *reinterpret_cast<float4*>(mem2o + off) =
                make_float4(mem2[0], mem2[1], mem2[2], mem2[3]);
            *reinterpret_cast<float4*>(curo + off) = cur4;
            *reinterpret_cast<float4*>(spk1o + off) =
                make_float4(spk1[0], spk1[1], spk1[2], spk1[3]);
            *reinterpret_cast<float4*>(mem1o + off) =
                make_float4(mem1[0], mem1[1], mem1[2], mem1[3]);
        }
    }
}

// ---------------------------------------------------------------------------
// Inputs: x[256*784], W1[100*784], b1[100], alpha1[1], beta1[1]  (all f32)
// Output: 5 sections of [T,B,H] f32: spk2, mem2, cur, spk1, mem1
// ---------------------------------------------------------------------------
extern "C" void kernel_launch(void* const* d_in, const int* in_sizes, int n_in,
                              void* d_out, int out_size) {
    const float* x      = (const float*)d_in[0];
    const float* W1     = (const float*)d_in[1];
    const float* b1     = (const float*)d_in[2];
    const float* alpha1 = (const float*)d_in[3];
    const float* beta1  = (const float*)d_in[4];
    float* out = (float*)d_out;

    // Reset sync flags (graph-capturable memset node; no allocation).
    void* flags_ptr = nullptr;
    cudaGetSymbolAddress(&flags_ptr, g_flags);
    cudaMemsetAsync(flags_ptr, 0, NCHUNK * 32 * sizeof(int));

    snn_fused<<<P1_BLOCKS + P2_BLOCKS, 128>>>(x, W1, b1, alpha1, beta1, out);
}

// round 10
// speedup vs baseline: 1.0969x; 1.0004x over previous
#include <cuda_runtime.h>
#include <cstddef>

#define BATCH 256
#define H 100
#define NIN 784
#define T 2500
#define BH (BATCH * H)                 // 25600
#define SEC ((size_t)T * (size_t)BH)   // 64,000,000 elements per section
#define NCHUNK 25
#define CHUNK 100                      // NCHUNK * CHUNK == T

#define P1_BLOCKS (BH / 128)           // 200 phase-1 blocks (1 cell/thread)
#define CELLS_PER_THREAD 4
#define P2_BLOCKS_PER_CHUNK (BH / (128 * CELLS_PER_THREAD))   // 50
#define P2_BLOCKS (NCHUNK * P2_BLOCKS_PER_CHUNK)              // 1250

// Scratch (no cudaMalloc allowed)
__device__ float  g_cur1[BH];
__device__ float4 g_ckpt[NCHUNK * BH];        // state at start of each chunk
__device__ int    g_flags[NCHUNK * 32];       // 1 flag per chunk, 128B apart

// ---------------------------------------------------------------------------
// Shared step function — identical in phase1/phase2 so replay from checkpoints
// is bit-identical to a monolithic run.
// ---------------------------------------------------------------------------
__device__ __forceinline__ void lif_step(const float a1, const float be1,
                                         const float cur,
                                         float& syn1, float& mem1,
                                         float& syn2, float& mem2,
                                         float& spk1, float& spk2) {
    const float keep1 = (mem1 > 1.0f) ? 0.0f : 1.0f;   // reset from PREVIOUS mem
    syn1 = fmaf(a1, syn1, cur);
    mem1 = fmaf(be1, mem1, syn1) * keep1;
    spk1 = (mem1 > 1.0f) ? 1.0f : 0.0f;
    const float keep2 = (mem2 > 1.0f) ? 0.0f : 1.0f;
    syn2 = fmaf(0.8f, syn2, spk1);
    mem2 = fmaf(0.9f, mem2, syn2) * keep2;
    spk2 = (mem2 > 1.0f) ? 1.0f : 0.0f;
}

// Poll with a plain volatile L2 load — NOT atomicAdd(ptr,0). Atomic polls
// serialize on the per-address LTS atomic ALU and starve the releasing
// increments (the R4/R7/R8 regression mechanism). Proven fix in R9.
__device__ __forceinline__ void spin_on_flag(const int* flag, int target) {
    while (*(volatile const int*)flag < target) __nanosleep(200);
}

// ---------------------------------------------------------------------------
// ONE fused kernel (R9 structure — the 218.9us asset — with two isolated
// changes: __stcs streaming output stores; chunk-0 skips the ckpt load):
//   blocks [0, P1_BLOCKS): phase 1 — fused gemm for 128 consecutive cells,
//     publish g_cur1, serial recurrence with checkpoints, release flag[c]
//     BEFORE computing chunk c.
//   blocks [P1_BLOCKS, ...): phase 2 — wait flag[c] (volatile poll), replay
//     CHUNK steps for 4 cells, __stcs float4 stores to all 5 sections.
// ---------------------------------------------------------------------------
__global__ void __launch_bounds__(128) snn_fused(const float* __restrict__ x,
                                                 const float* __restrict__ W1,
                                                 const float* __restrict__ b1,
                                                 const float* __restrict__ alpha1,
                                                 const float* __restrict__ beta1,
                                                 float* __restrict__ out) {
    const float a1  = fminf(fmaxf(alpha1[0], 0.0f), 1.0f);
    const float be1 = fminf(fmaxf(beta1[0], 0.0f), 1.0f);
    const int tid = threadIdx.x;

    if (blockIdx.x < P1_BLOCKS) {
        // ---------------- phase 1: fused GEMM ----------------
        __shared__ float xs[3 * NIN];          // up to 3 batch rows
        __shared__ float curs[128];
        const int cell0blk = blockIdx.x * 128;
        const int b0 = cell0blk / H;
        const int nb = ((cell0blk + 127) / H) - b0 + 1;    // 2 or 3

        for (int i = tid; i < nb * NIN; i += 128)
            xs[i] = x[(size_t)(b0 + i / NIN) * NIN + (i % NIN)];
        __syncthreads();

        const int warp = tid >> 5;
        const int lane = tid & 31;
        const int g  = lane >> 3;              // 4 cell-groups per warp-phase
        const int gl = lane & 7;               // lane within 8-lane group

#pragma unroll 1
        for (int p = 0; p < 8; p++) {
            const int lcell = warp * 32 + p * 4 + g;       // 0..127
            const int cid = cell0blk + lcell;
            const int cb = cid / H, ch = cid % H;
            const float4* __restrict__ w4 =
                reinterpret_cast<const float4*>(W1 + (size_t)ch * NIN);
            const float* __restrict__ xr = xs + (cb - b0) * NIN;

            float acc = 0.0f;
#pragma unroll
            for (int t = 0; t < 24; t++) {     // 196 float4 = 8*24 + 4
                const int j = gl + 8 * t;
                const float4 wv = w4[j];
                const int k = j * 4;
                acc = fmaf(wv.x, xr[k + 0], acc);
                acc = fmaf(wv.y, xr[k + 1], acc);
                acc = fmaf(wv.z, xr[k + 2], acc);
                acc = fmaf(wv.w, xr[k + 3], acc);
            }
            if (gl < 4) {                      // remainder float4 192..195
                const int j = 192 + gl;
                const float4 wv = w4[j];
                const int k = j * 4;
                acc = fmaf(wv.x, xr[k + 0], acc);
                acc = fmaf(wv.y, xr[k + 1], acc);
                acc = fmaf(wv.z, xr[k + 2], acc);
                acc = fmaf(wv.w, xr[k + 3], acc);
            }
            acc += __shfl_down_sync(0xFFFFFFFFu, acc, 4, 8);
            acc += __shfl_down_sync(0xFFFFFFFFu, acc, 2, 8);
            acc += __shfl_down_sync(0xFFFFFFFFu, acc, 1, 8);
            if (gl == 0) curs[lcell] = acc + b1[ch];
        }
        __syncthreads();

        const int cell = cell0blk + tid;
        const float cur = curs[tid];
        g_cur1[cell] = cur;                    // publish for phase 2

        // ---------------- phase 1: recurrence + checkpoints ----------------
        float syn1 = 0.f, mem1 = 0.f, syn2 = 0.f, mem2 = 0.f;
        float spk1, spk2;

        for (int c = 0; c < NCHUNK; c++) {
            if (c > 0)                         // chunk-0 state is known zeros
                g_ckpt[c * BH + cell] = make_float4(syn1, mem1, syn2, mem2);
            __threadfence();
            __syncthreads();                   // ckpt (and cur1) visible
            if (tid == 0) atomicAdd(&g_flags[c * 32], 1);
#pragma unroll 5
            for (int i = 0; i < CHUNK; i++)
                lif_step(a1, be1, cur, syn1, mem1, syn2, mem2, spk1, spk2);
        }
    } else {
        // ---------------- phase 2 ----------------
        const int idx = blockIdx.x - P1_BLOCKS;
        const int c = idx / P2_BLOCKS_PER_CHUNK;           // chunk-major order
        const int blk = idx % P2_BLOCKS_PER_CHUNK;
        const int cell0 = (blk * 128 + tid) * CELLS_PER_THREAD;

        if (tid == 0) spin_on_flag(&g_flags[c * 32], P1_BLOCKS);
        __syncthreads();
        __threadfence();

        const float4 cur4 = *reinterpret_cast<const float4*>(g_cur1 + cell0);
        float cur[4] = {cur4.x, cur4.y, cur4.z, cur4.w};

        float syn1[4], mem1[4], syn2[4], mem2[4], spk1[4], spk2[4];
        if (c == 0) {
#pragma unroll
            for (int j = 0; j < 4; j++) {
                syn1[j] = 0.f; mem1[j] = 0.f; syn2[j] = 0.f; mem2[j] = 0.f;
            }
        } else {
#pragma unroll
            for (int j = 0; j < 4; j++) {
                float4 st = g_ckpt[c * BH + cell0 + j];
                syn1[j] = st.x; mem1[j] = st.y; syn2[j] = st.z; mem2[j] = st.w;
            }
        }

        float* __restrict__ spk2o = out;
        float* __restrict__ mem2o = out + SEC;
        float* __restrict__ curo  = out + 2 * SEC;
        float* __restrict__ spk1o = out + 3 * SEC;
        float* __restrict__ mem1o = out + 4 * SEC;

        size_t off = (size_t)(c * CHUNK) * BH + cell0;
#pragma unroll 2
        for (int i = 0; i < CHUNK; i++, off += BH) {
#pragma unroll
            for (int j = 0; j < 4; j++)
                lif_step(a1, be1, cur[j], syn1[j], mem1[j], syn2[j], mem2[j],
                         spk1[j], spk2[j]);
            __stcs(reinterpret_cast<float4*>(spk2o + off),
                   make_float4(spk2[0], spk2[1], spk2[2], spk2[3]));
            __stcs(reinterpret_cast<float4*>(mem2o + off),
                   make_float4(mem2[0], mem2[1], mem2[2], mem2[3]));
            __stcs(reinterpret_cast<float4*>(curo + off), cur4);
            __stcs(reinterpret_cast<float4*>(spk1o + off),
                   make_float4(spk1[0], spk1[1], spk1[2], spk1[3]));
            __stcs(reinterpret_cast<float4*>(mem1o + off),
                   make_float4(mem1[0], mem1[1], mem1[2], mem1[3]));
        }
    }
}

// ---------------------------------------------------------------------------
// Inputs: x[256*784], W1[100*784], b1[100], alpha1[1], beta1[1]  (all f32)
// Output: 5 sections of [T,B,H] f32: spk2, mem2, cur, spk1, mem1
// ---------------------------------------------------------------------------
extern "C" void kernel_launch(void* const* d_in, const int* in_sizes, int n_in,
                              void* d_out, int out_size) {
    const float* x      = (const float*)d_in[0];
    const float* W1     = (const float*)d_in[1];
    const float* b1     = (const float*)d_in[2];
    const float* alpha1 = (const float*)d_in[3];
    const float* beta1  = (const float*)d_in[4];
    float* out = (float*)d_out;

    // Reset sync flags (graph-capturable memset node; no allocation).
    void* flags_ptr = nullptr;
    cudaGetSymbolAddress(&flags_ptr, g_flags);
    cudaMemsetAsync(flags_ptr, 0, NCHUNK * 32 * sizeof(int));

    snn_fused<<<P1_BLOCKS + P2_BLOCKS, 128>>>(x, W1, b1, alpha1, beta1, out);
}